// round 1
// baseline (speedup 1.0000x reference)
#include <cuda_runtime.h>
#include <math_constants.h>

// Causal attention head: out = softmax(causal(Q K^T / sqrt(D))) V
// B=4, L=4096, D=128, fp32. Flash-attention-2 style SIMT tiling.
//
// Tiling: Br=Bc=64, 256 threads (16x16). Thread (ty,tx):
//   S fragment: rows 4ty..4ty+3, cols 4tx..4tx+3   (4x4)
//   O fragment: rows 4ty..4ty+3, cols 8tx..8tx+7   (4x8)
// Q,K stored transposed in smem ([D][64]) -> conflict-free float4 loads in S loop.
// Row-softmax stats reduced across the 16-thread row group (half warp) via shfl,
// so alpha / l live in registers for the O update (same ty -> same rows).

namespace {
constexpr int Bq = 64;
constexpr int Bk = 64;
constexpr int HD = 128;
constexpr int SEQ = 4096;
constexpr int NB = 4;
constexpr int NTHREADS = 256;
// Qt[128][64] + Kt[128][64] + Vs[64][128] + Ps[64][64]
constexpr int SMEM_FLOATS = HD * 64 + HD * 64 + 64 * HD + 64 * 64;  // 28672 -> 112KB
}  // namespace

__global__ __launch_bounds__(NTHREADS, 2)
void fa_fp32_kernel(const float* __restrict__ Kg_, const float* __restrict__ Qg_,
                    const float* __restrict__ Vg_, float* __restrict__ Og_) {
  extern __shared__ float sm[];
  float* Qt = sm;                // [HD][64] transposed
  float* Kt = Qt + HD * 64;      // [HD][64] transposed
  float* Vs = Kt + HD * 64;      // [64][HD] row-major
  float* Ps = Vs + 64 * HD;      // [64][64] row-major

  const int qt = blockIdx.x;
  const int b = blockIdx.y;
  const int q0 = qt * Bq;
  const int tid = threadIdx.x;
  const int tx = tid & 15;
  const int ty = tid >> 4;

  // ---- load Q tile transposed into Qt (once per block) ----
  {
    const float* Qg = Qg_ + ((size_t)b * SEQ + q0) * HD;
    const int r = tid >> 2;       // row 0..63
    const int c0 = tid & 3;       // float4 chunk phase
#pragma unroll
    for (int it = 0; it < 8; ++it) {
      const int c = (it << 2) + c0;  // float4 chunk 0..31 (d = 4c)
      const float4 v = reinterpret_cast<const float4*>(Qg + r * HD)[c];
      Qt[(4 * c + 0) * 64 + r] = v.x;
      Qt[(4 * c + 1) * 64 + r] = v.y;
      Qt[(4 * c + 2) * 64 + r] = v.z;
      Qt[(4 * c + 3) * 64 + r] = v.w;
    }
  }

  float o[4][8];
#pragma unroll
  for (int i = 0; i < 4; ++i)
#pragma unroll
    for (int j = 0; j < 8; ++j) o[i][j] = 0.f;

  float m_run[4], l_run[4];
#pragma unroll
  for (int i = 0; i < 4; ++i) {
    m_run[i] = -CUDART_INF_F;
    l_run[i] = 0.f;
  }

  const float scale = 0.088388347648318447f;  // 1/sqrt(128)

  for (int kt = 0; kt <= qt; ++kt) {
    const int k0 = kt * Bk;
    __syncthreads();  // protect Kt/Vs/Ps from previous iteration's readers

    // ---- load K tile transposed, V tile direct ----
    {
      const float* Kg = Kg_ + ((size_t)b * SEQ + k0) * HD;
      const int r = tid >> 2;
      const int c0 = tid & 3;
#pragma unroll
      for (int it = 0; it < 8; ++it) {
        const int c = (it << 2) + c0;
        const float4 v = reinterpret_cast<const float4*>(Kg + r * HD)[c];
        Kt[(4 * c + 0) * 64 + r] = v.x;
        Kt[(4 * c + 1) * 64 + r] = v.y;
        Kt[(4 * c + 2) * 64 + r] = v.z;
        Kt[(4 * c + 3) * 64 + r] = v.w;
      }
      const float4* Vg4 =
          reinterpret_cast<const float4*>(Vg_ + ((size_t)b * SEQ + k0) * HD);
      float4* Vs4 = reinterpret_cast<float4*>(Vs);
#pragma unroll
      for (int it = 0; it < 8; ++it) Vs4[tid + it * NTHREADS] = Vg4[tid + it * NTHREADS];
    }
    __syncthreads();

    // ---- S = Q K^T (4x4 fragment) ----
    float s[4][4];
#pragma unroll
    for (int i = 0; i < 4; ++i)
#pragma unroll
      for (int j = 0; j < 4; ++j) s[i][j] = 0.f;

    const float4* Qt4 = reinterpret_cast<const float4*>(Qt) + ty;
    const float4* Kt4 = reinterpret_cast<const float4*>(Kt) + tx;
#pragma unroll 8
    for (int d = 0; d < HD; ++d) {
      const float4 qv = Qt4[d * 16];
      const float4 kv = Kt4[d * 16];
      const float qa[4] = {qv.x, qv.y, qv.z, qv.w};
      const float ka[4] = {kv.x, kv.y, kv.z, kv.w};
#pragma unroll
      for (int i = 0; i < 4; ++i)
#pragma unroll
        for (int j = 0; j < 4; ++j) s[i][j] = fmaf(qa[i], ka[j], s[i][j]);
    }

    // ---- scale + causal mask (diagonal tile only) ----
    if (kt == qt) {
#pragma unroll
      for (int i = 0; i < 4; ++i)
#pragma unroll
        for (int j = 0; j < 4; ++j)
          s[i][j] = (4 * tx + j > 4 * ty + i) ? -CUDART_INF_F : s[i][j] * scale;
    } else {
#pragma unroll
      for (int i = 0; i < 4; ++i)
#pragma unroll
        for (int j = 0; j < 4; ++j) s[i][j] *= scale;
    }

    // ---- online softmax: row group = 16 threads (half warp, same ty) ----
    float alpha[4];
#pragma unroll
    for (int i = 0; i < 4; ++i) {
      float mx = fmaxf(fmaxf(s[i][0], s[i][1]), fmaxf(s[i][2], s[i][3]));
#pragma unroll
      for (int w = 8; w >= 1; w >>= 1)
        mx = fmaxf(mx, __shfl_xor_sync(0xffffffffu, mx, w));
      const float m_new = fmaxf(m_run[i], mx);
      alpha[i] = __expf(m_run[i] - m_new);  // first tile: exp(-inf)=0
      float rs = 0.f;
#pragma unroll
      for (int j = 0; j < 4; ++j) {
        s[i][j] = __expf(s[i][j] - m_new);  // masked: exp(-inf)=0
        rs += s[i][j];
      }
#pragma unroll
      for (int w = 8; w >= 1; w >>= 1) rs += __shfl_xor_sync(0xffffffffu, rs, w);
      l_run[i] = l_run[i] * alpha[i] + rs;
      m_run[i] = m_new;
    }

    // ---- store P fragment (contiguous float4 across tx: conflict-free) ----
#pragma unroll
    for (int i = 0; i < 4; ++i) {
      reinterpret_cast<float4*>(Ps)[(4 * ty + i) * 16 + tx] =
          make_float4(s[i][0], s[i][1], s[i][2], s[i][3]);
    }
    __syncthreads();

    // ---- O = O*alpha + P V (4x8 fragment) ----
#pragma unroll
    for (int i = 0; i < 4; ++i)
#pragma unroll
      for (int j = 0; j < 8; ++j) o[i][j] *= alpha[i];

    const float4* Vrd = reinterpret_cast<const float4*>(Vs) + tx * 2;
    const float* Prd = Ps + (4 * ty) * 64;
#pragma unroll 4
    for (int k = 0; k < Bk; ++k) {
      const float p[4] = {Prd[k], Prd[64 + k], Prd[128 + k], Prd[192 + k]};
      const float4 v0 = Vrd[k * 32];
      const float4 v1 = Vrd[k * 32 + 1];
      const float va[8] = {v0.x, v0.y, v0.z, v0.w, v1.x, v1.y, v1.z, v1.w};
#pragma unroll
      for (int i = 0; i < 4; ++i)
#pragma unroll
        for (int j = 0; j < 8; ++j) o[i][j] = fmaf(p[i], va[j], o[i][j]);
    }
  }

  // ---- normalize and write out ----
  float* Og = Og_ + ((size_t)b * SEQ + q0) * HD;
#pragma unroll
  for (int i = 0; i < 4; ++i) {
    const float inv = 1.f / l_run[i];
    float4 r0 = make_float4(o[i][0] * inv, o[i][1] * inv, o[i][2] * inv, o[i][3] * inv);
    float4 r1 = make_float4(o[i][4] * inv, o[i][5] * inv, o[i][6] * inv, o[i][7] * inv);
    float4* dst = reinterpret_cast<float4*>(Og + (4 * ty + i) * HD) + tx * 2;
    dst[0] = r0;
    dst[1] = r1;
  }
}

extern "C" void kernel_launch(void* const* d_in, const int* in_sizes, int n_in,
                              void* d_out, int out_size) {
  // metadata order matches setup_inputs dict: key, query, value
  const float* Kg = (const float*)d_in[0];
  const float* Qg = (const float*)d_in[1];
  const float* Vg = (const float*)d_in[2];
  float* Og = (float*)d_out;

  const int smem_bytes = SMEM_FLOATS * sizeof(float);  // 114688
  cudaFuncSetAttribute(fa_fp32_kernel, cudaFuncAttributeMaxDynamicSharedMemorySize,
                       smem_bytes);

  dim3 grid(SEQ / Bq, NB);
  fa_fp32_kernel<<<grid, NTHREADS, smem_bytes>>>(Kg, Qg, Vg, Og);
}